// round 1
// baseline (speedup 1.0000x reference)
#include <cuda_runtime.h>
#include <math.h>

// Problem: LineFinderLoss. S = 4096 (square). Outputs: (loss scalar, cost[S,S])
// packed in tuple order: d_out[0] = loss, d_out[1 + i*S + j] = cost[i][j].
//
// cost[i][j] = 0.5*((in[i,0]-tg[j,0])^2 + (in[i,1]-tg[j,1])^2)
// loss = ALPHA*sum((in-tg)^2) - S*sum_n log(in[n,4]) + sum_ij (in[j,3]-tg[i,j])^2 / S^2

#define MAXS 4096
#define ALPHA 0.01

// ---------------- device scratch (no allocations allowed) ----------------
__device__ float  g_t0[MAXS];     // target[:,0]
__device__ float  g_t1[MAXS];     // target[:,1]
__device__ float  g_ic3[MAXS];    // input[:,3]
__device__ double g_sumlog;       // sum_n log(input[n,4])
__device__ double g_part_sq[MAXS];   // per-row partial of sum((in-tg)^2)
__device__ double g_part_t3[MAXS];   // per-row partial of sum((in[j,3]-tg[i,j])^2)

// ---------------- kernel 0: zero the atomic accumulator ----------------
__global__ void zero_kernel() {
    g_sumlog = 0.0;
}

// ---------------- kernel 1: gather columns + reduce sum(log) ----------------
__global__ void pack_kernel(const float* __restrict__ inp,
                            const float* __restrict__ tgt, int S) {
    int r = blockIdx.x * blockDim.x + threadIdx.x;
    float lg = 0.0f;
    if (r < S) {
        size_t base = (size_t)r * S;
        g_t0[r]  = tgt[base + 0];
        g_t1[r]  = tgt[base + 1];
        g_ic3[r] = inp[base + 3];
        lg = logf(inp[base + 4]);
    }
    // warp reduce
    #pragma unroll
    for (int off = 16; off > 0; off >>= 1)
        lg += __shfl_down_sync(0xffffffffu, lg, off);
    __shared__ float warp_sums[8];
    int lane = threadIdx.x & 31;
    int wid  = threadIdx.x >> 5;
    if (lane == 0) warp_sums[wid] = lg;
    __syncthreads();
    if (threadIdx.x == 0) {
        float s = 0.0f;
        int nw = (blockDim.x + 31) >> 5;
        for (int w = 0; w < nw; w++) s += warp_sums[w];
        atomicAdd(&g_sumlog, (double)s);
    }
}

// ---------------- kernel 2: fused stream pass ----------------
// One block per row i. Reads input row + target row (float4, coalesced),
// column vectors from packed L2-resident arrays, writes cost row, and
// accumulates the two big reduction sums.
__global__ __launch_bounds__(256, 8)
void main_kernel(const float* __restrict__ inp,
                 const float* __restrict__ tgt,
                 float* __restrict__ cost, int S) {
    const int i = blockIdx.x;
    const size_t rowoff = (size_t)i * S;
    const float a0 = inp[rowoff + 0];
    const float a1 = inp[rowoff + 1];

    const float4* __restrict__ in4 = (const float4*)(inp + rowoff);
    const float4* __restrict__ tg4 = (const float4*)(tgt + rowoff);
    const float4* __restrict__ t04 = (const float4*)g_t0;
    const float4* __restrict__ t14 = (const float4*)g_t1;
    const float4* __restrict__ c34 = (const float4*)g_ic3;
    float* __restrict__ crow = cost + rowoff;

    float acc_sq = 0.0f;   // sum (in - tg)^2 for this row
    float acc_t3 = 0.0f;   // sum (ic3[j] - tg)^2 for this row

    const int n4 = S >> 2;
    for (int j = threadIdx.x; j < n4; j += blockDim.x) {
        float4 in = in4[j];
        float4 tg = tg4[j];
        float4 t0 = t04[j];
        float4 t1 = t14[j];
        float4 c3 = c34[j];

        float d, e, u, v;
        d = in.x - tg.x; acc_sq = fmaf(d, d, acc_sq);
        e = c3.x - tg.x; acc_t3 = fmaf(e, e, acc_t3);
        u = a0 - t0.x; v = a1 - t1.x;
        crow[4*j + 0] = 0.5f * fmaf(u, u, v*v);

        d = in.y - tg.y; acc_sq = fmaf(d, d, acc_sq);
        e = c3.y - tg.y; acc_t3 = fmaf(e, e, acc_t3);
        u = a0 - t0.y; v = a1 - t1.y;
        crow[4*j + 1] = 0.5f * fmaf(u, u, v*v);

        d = in.z - tg.z; acc_sq = fmaf(d, d, acc_sq);
        e = c3.z - tg.z; acc_t3 = fmaf(e, e, acc_t3);
        u = a0 - t0.z; v = a1 - t1.z;
        crow[4*j + 2] = 0.5f * fmaf(u, u, v*v);

        d = in.w - tg.w; acc_sq = fmaf(d, d, acc_sq);
        e = c3.w - tg.w; acc_t3 = fmaf(e, e, acc_t3);
        u = a0 - t0.w; v = a1 - t1.w;
        crow[4*j + 3] = 0.5f * fmaf(u, u, v*v);
    }

    // block reduce (both accumulators)
    #pragma unroll
    for (int off = 16; off > 0; off >>= 1) {
        acc_sq += __shfl_down_sync(0xffffffffu, acc_sq, off);
        acc_t3 += __shfl_down_sync(0xffffffffu, acc_t3, off);
    }
    __shared__ float s_sq[8], s_t3[8];
    int lane = threadIdx.x & 31;
    int wid  = threadIdx.x >> 5;
    if (lane == 0) { s_sq[wid] = acc_sq; s_t3[wid] = acc_t3; }
    __syncthreads();
    if (threadIdx.x == 0) {
        float r1 = 0.0f, r2 = 0.0f;
        #pragma unroll
        for (int w = 0; w < 8; w++) { r1 += s_sq[w]; r2 += s_t3[w]; }
        g_part_sq[i] = (double)r1;
        g_part_t3[i] = (double)r2;
    }
}

// ---------------- kernel 3: final reduce + loss ----------------
__global__ void final_kernel(float* __restrict__ out, int S) {
    __shared__ double sh1[256], sh2[256];
    double a = 0.0, b = 0.0;
    for (int i = threadIdx.x; i < S; i += blockDim.x) {
        a += g_part_sq[i];
        b += g_part_t3[i];
    }
    sh1[threadIdx.x] = a;
    sh2[threadIdx.x] = b;
    __syncthreads();
    for (int off = 128; off > 0; off >>= 1) {
        if (threadIdx.x < off) {
            sh1[threadIdx.x] += sh1[threadIdx.x + off];
            sh2[threadIdx.x] += sh2[threadIdx.x + off];
        }
        __syncthreads();
    }
    if (threadIdx.x == 0) {
        double sumsq  = sh1[0];
        double sum3   = sh2[0];
        double sumlog = g_sumlog;
        double Sd = (double)S;
        double loss = ALPHA * sumsq - Sd * sumlog + sum3 / (Sd * Sd);
        out[0] = (float)loss;
    }
}

// ---------------- launch ----------------
extern "C" void kernel_launch(void* const* d_in, const int* in_sizes, int n_in,
                              void* d_out, int out_size) {
    const float* inp = (const float*)d_in[0];
    const float* tgt = (const float*)d_in[1];
    float* out = (float*)d_out;

    // S from element count (square matrices)
    long long n = in_sizes[0];
    int S = 1;
    while ((long long)(S + 1) * (S + 1) <= n) S++;  // integer sqrt
    if (S > MAXS) S = MAXS;

    zero_kernel<<<1, 1>>>();
    pack_kernel<<<(S + 255) / 256, 256>>>(inp, tgt, S);
    main_kernel<<<S, 256>>>(inp, tgt, out + 1, S);
    final_kernel<<<1, 256>>>(out, S);
}

// round 2
// speedup vs baseline: 1.1870x; 1.1870x over previous
#include <cuda_runtime.h>
#include <math.h>

// LineFinderLoss, S = 4096 (square). Output tuple packed: d_out[0] = loss,
// d_out[1 + i*S + j] = cost[i][j].
//
// cost[i][j] = 0.5*((in[i,0]-tg[j,0])^2 + (in[i,1]-tg[j,1])^2)
// loss = ALPHA*sum((in-tg)^2) - S*sum_n log(in[n,4]) + sum_ij (in[j,3]-tg[i,j])^2 / S^2

#define MAXS   4096
#define ALPHA  0.01
#define RTILE  16      // rows per block
#define CTILE  1024    // cols per block (256 threads * 4)

// ---------------- device scratch (no allocations allowed) ----------------
// Shifted packed columns: g_t0s[k] = target[k-1, 0]  (k = 1..S), g_t0s[0] junk.
__device__ float  g_t0s[MAXS + 4];
__device__ float  g_t1s[MAXS + 4];
__device__ float  g_ic3[MAXS + 4];     // input[:,3] (unshifted)
__device__ double g_lgpart[MAXS / 256];// per-pack-block partial of sum log(in[:,4])
__device__ double g_sum_sq;            // zero-init; reset by finishing block
__device__ double g_sum_t3;
__device__ unsigned int g_count;

// ---------------- kernel 1: gather columns + partial sum(log) ----------------
__global__ void pack_kernel(const float* __restrict__ inp,
                            const float* __restrict__ tgt, int S) {
    int r = blockIdx.x * blockDim.x + threadIdx.x;
    float lg = 0.0f;
    if (r < S) {
        size_t base = (size_t)r * S;
        float t0 = tgt[base + 0];
        float t1 = tgt[base + 1];
        g_t0s[r + 1] = t0;
        g_t1s[r + 1] = t1;
        g_ic3[r]     = inp[base + 3];
        lg = logf(inp[base + 4]);
        if (r == 0) { g_t0s[0] = 0.0f; g_t1s[0] = 0.0f; }
    }
    // block reduce lg
    #pragma unroll
    for (int off = 16; off > 0; off >>= 1)
        lg += __shfl_down_sync(0xffffffffu, lg, off);
    __shared__ float ws[8];
    int lane = threadIdx.x & 31, wid = threadIdx.x >> 5;
    if (lane == 0) ws[wid] = lg;
    __syncthreads();
    if (threadIdx.x == 0) {
        float s = 0.0f;
        #pragma unroll
        for (int w = 0; w < 8; w++) s += ws[w];
        g_lgpart[blockIdx.x] = (double)s;
    }
}

// ---------------- kernel 2: tiled stream pass + fused finalize ----------------
// Block = 256 threads covering CTILE=1024 columns (float4 each) x RTILE=16 rows.
// Column data (t0s/t1s/c3) loaded ONCE per block into registers, reused 16x.
// Cost stores: thread j4 writes cols [4*j4-1 .. 4*j4+2] as an aligned float4
// at (out + row*S + 4*j4), because out[0] is the loss scalar and cost starts
// at out+1. Shifted t0s/t1s arrays keep those loads aligned too.
__global__ __launch_bounds__(256, 8)
void main_kernel(const float* __restrict__ inp,
                 const float* __restrict__ tgt,
                 float* __restrict__ out, int S) {
    const int j4   = blockIdx.x * 256 + threadIdx.x;   // global float4 col idx
    const int row0 = blockIdx.y * RTILE;
    const int lastj4 = (S >> 2) - 1;

    __shared__ float sa0[RTILE], sa1[RTILE];
    if (threadIdx.x < RTILE) {
        size_t b = (size_t)(row0 + threadIdx.x) * S;
        sa0[threadIdx.x] = inp[b + 0];
        sa1[threadIdx.x] = inp[b + 1];
    }
    __syncthreads();

    // column-resident data (registers, reused across all 16 rows)
    const float4 t0s = ((const float4*)g_t0s)[j4];  // t0[4j-1..4j+2]
    const float4 t1s = ((const float4*)g_t1s)[j4];
    const float4 c3  = ((const float4*)g_ic3)[j4];  // in[4j..4j+3, 3]
    float t0L = 0.0f, t1L = 0.0f;
    if (j4 == lastj4) { t0L = g_t0s[S]; t1L = g_t1s[S]; }

    float acc_sq = 0.0f, acc_t3 = 0.0f;

    #pragma unroll 4
    for (int r = 0; r < RTILE; r++) {
        const int row = row0 + r;
        const size_t base = (size_t)row * S;
        const float4 in = ((const float4*)(inp + base))[j4];
        const float4 tg = ((const float4*)(tgt + base))[j4];
        const float a0 = sa0[r], a1 = sa1[r];

        float d, e;
        d = in.x - tg.x; acc_sq = fmaf(d, d, acc_sq);
        e = c3.x - tg.x; acc_t3 = fmaf(e, e, acc_t3);
        d = in.y - tg.y; acc_sq = fmaf(d, d, acc_sq);
        e = c3.y - tg.y; acc_t3 = fmaf(e, e, acc_t3);
        d = in.z - tg.z; acc_sq = fmaf(d, d, acc_sq);
        e = c3.z - tg.z; acc_t3 = fmaf(e, e, acc_t3);
        d = in.w - tg.w; acc_sq = fmaf(d, d, acc_sq);
        e = c3.w - tg.w; acc_t3 = fmaf(e, e, acc_t3);

        // cost for cols [4*j4-1 .. 4*j4+2]
        float4 cv;
        float u, v;
        u = a0 - t0s.x; v = a1 - t1s.x; cv.x = 0.5f * fmaf(u, u, v * v);
        u = a0 - t0s.y; v = a1 - t1s.y; cv.y = 0.5f * fmaf(u, u, v * v);
        u = a0 - t0s.z; v = a1 - t1s.z; cv.z = 0.5f * fmaf(u, u, v * v);
        u = a0 - t0s.w; v = a1 - t1s.w; cv.w = 0.5f * fmaf(u, u, v * v);

        if (j4 > 0) {
            // address out + base + 4*j4  == cost + base + (4*j4 - 1), 16B aligned
            ((float4*)(out + base))[j4] = cv;
        } else {
            float* crow = out + 1 + base;   // cost row start
            crow[0] = cv.y; crow[1] = cv.z; crow[2] = cv.w;
        }
        if (j4 == lastj4) {
            u = a0 - t0L; v = a1 - t1L;
            out[1 + base + (size_t)(S - 1)] = 0.5f * fmaf(u, u, v * v);
        }
    }

    // block reduce
    #pragma unroll
    for (int off = 16; off > 0; off >>= 1) {
        acc_sq += __shfl_down_sync(0xffffffffu, acc_sq, off);
        acc_t3 += __shfl_down_sync(0xffffffffu, acc_t3, off);
    }
    __shared__ float s_sq[8], s_t3[8];
    int lane = threadIdx.x & 31, wid = threadIdx.x >> 5;
    if (lane == 0) { s_sq[wid] = acc_sq; s_t3[wid] = acc_t3; }
    __syncthreads();

    __shared__ bool amLast;
    if (threadIdx.x == 0) {
        float r1 = 0.0f, r2 = 0.0f;
        #pragma unroll
        for (int w = 0; w < 8; w++) { r1 += s_sq[w]; r2 += s_t3[w]; }
        atomicAdd(&g_sum_sq, (double)r1);
        atomicAdd(&g_sum_t3, (double)r2);
        __threadfence();
        unsigned int total = gridDim.x * gridDim.y;
        unsigned int ticket = atomicAdd(&g_count, 1u);
        amLast = (ticket == total - 1);
    }
    __syncthreads();

    // finishing block computes the loss scalar and resets replay state
    if (amLast && threadIdx.x == 0) {
        double sumsq  = *((volatile double*)&g_sum_sq);
        double sum3   = *((volatile double*)&g_sum_t3);
        double sumlog = 0.0;
        int nlg = S / 256;
        for (int w = 0; w < nlg; w++) sumlog += g_lgpart[w];
        double Sd = (double)S;
        out[0] = (float)(ALPHA * sumsq - Sd * sumlog + sum3 / (Sd * Sd));
        // reset for next graph replay
        g_sum_sq = 0.0; g_sum_t3 = 0.0;
        __threadfence();
        g_count = 0u;
    }
}

// ---------------- launch ----------------
extern "C" void kernel_launch(void* const* d_in, const int* in_sizes, int n_in,
                              void* d_out, int out_size) {
    const float* inp = (const float*)d_in[0];
    const float* tgt = (const float*)d_in[1];
    float* out = (float*)d_out;

    long long n = in_sizes[0];
    int S = 1;
    while ((long long)(S + 1) * (S + 1) <= n) S++;   // integer sqrt (S = 4096)
    if (S > MAXS) S = MAXS;

    pack_kernel<<<S / 256, 256>>>(inp, tgt, S);
    dim3 grid(S / CTILE, S / RTILE);
    main_kernel<<<grid, 256>>>(inp, tgt, out, S);
}

// round 4
// speedup vs baseline: 1.3746x; 1.1581x over previous
#include <cuda_runtime.h>
#include <math.h>

// LineFinderLoss, S = 4096 (square). Output tuple packed: d_out[0] = loss,
// d_out[1 + i*S + j] = cost[i][j].
//
// cost[i][j] = 0.5*((in[i,0]-tg[j,0])^2 + (in[i,1]-tg[j,1])^2)
// loss = ALPHA*sum((in-tg)^2) - S*sum_n log(in[n,4]) + sum_ij (in[j,3]-tg[i,j])^2 / S^2

#define MAXS    4096
#define ALPHA   0.01
#define RTILE   4        // rows per tile
#define CSLICES 4        // column slices (S / (256 threads * 4 floats))
#define GRID    1184     // 148 SMs * 8 resident blocks

// ---------------- device scratch (no allocations allowed) ----------------
// Shifted packed columns: g_t0s[k] = target[k-1, 0]  (k = 1..S), g_t0s[0] junk.
__device__ float  g_t0s[MAXS + 4];
__device__ float  g_t1s[MAXS + 4];
__device__ float  g_ic3[MAXS + 4];       // input[:,3] (unshifted)
__device__ double g_lgpart[MAXS / 256];  // per-pack-block partial of sum log(in[:,4])
__device__ double g_sum_sq;
__device__ double g_sum_t3;
__device__ unsigned int g_ticket;        // dynamic tile counter
__device__ unsigned int g_count;         // completion counter

// ---------------- kernel 1: reset state + gather columns + partial log-sum --
// Runs strictly before main_kernel on the same stream every replay, so the
// state reset here is ordered by the kernel boundary — main_kernel never
// mutates replay state.
__global__ void pack_kernel(const float* __restrict__ inp,
                            const float* __restrict__ tgt, int S) {
    if (blockIdx.x == 0 && threadIdx.x == 0) {
        g_ticket = 0u;
        g_count  = 0u;
        g_sum_sq = 0.0;
        g_sum_t3 = 0.0;
    }
    int r = blockIdx.x * blockDim.x + threadIdx.x;
    float lg = 0.0f;
    if (r < S) {
        size_t base = (size_t)r * S;
        g_t0s[r + 1] = tgt[base + 0];
        g_t1s[r + 1] = tgt[base + 1];
        g_ic3[r]     = inp[base + 3];
        lg = logf(inp[base + 4]);
        if (r == 0) { g_t0s[0] = 0.0f; g_t1s[0] = 0.0f; }
    }
    #pragma unroll
    for (int off = 16; off > 0; off >>= 1)
        lg += __shfl_down_sync(0xffffffffu, lg, off);
    __shared__ float ws[8];
    int lane = threadIdx.x & 31, wid = threadIdx.x >> 5;
    if (lane == 0) ws[wid] = lg;
    __syncthreads();
    if (threadIdx.x == 0) {
        float s = 0.0f;
        #pragma unroll
        for (int w = 0; w < 8; w++) s += ws[w];
        g_lgpart[blockIdx.x] = (double)s;
    }
}

// ---------------- kernel 2: persistent, dynamically-balanced stream pass ---
// 1184 resident blocks pop 4-row x 1024-col tiles from a global ticket.
// The pop loop is HARD-BOUNDED (ntiles+2 iterations) so the kernel terminates
// in bounded time regardless of counter state — worst case wrong answer, never
// a hang. Cost stores: thread j4 writes cols [4*j4-1 .. 4*j4+2] as an aligned
// float4 at (out + row*S + 4*j4) since out[0] is the loss scalar; pre-shifted
// t0s/t1s keep the matching loads aligned.
__global__ __launch_bounds__(256, 8)
void main_kernel(const float* __restrict__ inp,
                 const float* __restrict__ tgt,
                 float* __restrict__ out, int S) {
    const int tid    = threadIdx.x;
    const int lastj4 = (S >> 2) - 1;
    const int ntiles = CSLICES * (S / RTILE);

    __shared__ unsigned int sh_t;
    float acc_sq = 0.0f, acc_t3 = 0.0f;

    for (int safety = 0; safety < ntiles + 2; safety++) {
        if (tid == 0) sh_t = atomicAdd(&g_ticket, 1u);
        __syncthreads();
        const unsigned int t = sh_t;
        __syncthreads();
        if (t >= (unsigned int)ntiles) break;

        const int cs   = (int)(t & (CSLICES - 1));
        const int row0 = (int)(t >> 2) * RTILE;
        const int j4   = cs * 256 + tid;

        // column-resident data (L2 hits), reused across RTILE rows
        const float4 t0s = ((const float4*)g_t0s)[j4];  // t0[4j-1..4j+2]
        const float4 t1s = ((const float4*)g_t1s)[j4];
        const float4 c3  = ((const float4*)g_ic3)[j4];  // in[4j..4j+3, 3]

        #pragma unroll
        for (int r = 0; r < RTILE; r++) {
            const size_t base = (size_t)(row0 + r) * S;
            const float4 in = __ldcs((const float4*)(inp + base) + j4);
            const float4 tg = __ldcs((const float4*)(tgt + base) + j4);
            const float a0 = __ldg(inp + base);       // uniform broadcast
            const float a1 = __ldg(inp + base + 1);

            float d, e;
            d = in.x - tg.x; acc_sq = fmaf(d, d, acc_sq);
            e = c3.x - tg.x; acc_t3 = fmaf(e, e, acc_t3);
            d = in.y - tg.y; acc_sq = fmaf(d, d, acc_sq);
            e = c3.y - tg.y; acc_t3 = fmaf(e, e, acc_t3);
            d = in.z - tg.z; acc_sq = fmaf(d, d, acc_sq);
            e = c3.z - tg.z; acc_t3 = fmaf(e, e, acc_t3);
            d = in.w - tg.w; acc_sq = fmaf(d, d, acc_sq);
            e = c3.w - tg.w; acc_t3 = fmaf(e, e, acc_t3);

            float4 cv;
            float u, v;
            u = a0 - t0s.x; v = a1 - t1s.x; cv.x = 0.5f * fmaf(u, u, v * v);
            u = a0 - t0s.y; v = a1 - t1s.y; cv.y = 0.5f * fmaf(u, u, v * v);
            u = a0 - t0s.z; v = a1 - t1s.z; cv.z = 0.5f * fmaf(u, u, v * v);
            u = a0 - t0s.w; v = a1 - t1s.w; cv.w = 0.5f * fmaf(u, u, v * v);

            if (j4 > 0) {
                // out + base + 4*j4 == cost + base + (4*j4 - 1), 16B aligned
                __stcs((float4*)(out + base) + j4, cv);
            } else {
                float* crow = out + 1 + base;   // cost row start (cols 0..2)
                crow[0] = cv.y; crow[1] = cv.z; crow[2] = cv.w;
            }
            if (j4 == lastj4) {
                u = a0 - g_t0s[S]; v = a1 - g_t1s[S];
                out[1 + base + (size_t)(S - 1)] = 0.5f * fmaf(u, u, v * v);
            }
        }
    }

    // block reduce (after all tiles)
    #pragma unroll
    for (int off = 16; off > 0; off >>= 1) {
        acc_sq += __shfl_down_sync(0xffffffffu, acc_sq, off);
        acc_t3 += __shfl_down_sync(0xffffffffu, acc_t3, off);
    }
    __shared__ float s_sq[8], s_t3[8];
    int lane = threadIdx.x & 31, wid = threadIdx.x >> 5;
    if (lane == 0) { s_sq[wid] = acc_sq; s_t3[wid] = acc_t3; }
    __syncthreads();

    __shared__ bool amLast;
    if (threadIdx.x == 0) {
        float r1 = 0.0f, r2 = 0.0f;
        #pragma unroll
        for (int w = 0; w < 8; w++) { r1 += s_sq[w]; r2 += s_t3[w]; }
        atomicAdd(&g_sum_sq, (double)r1);
        atomicAdd(&g_sum_t3, (double)r2);
        __threadfence();
        unsigned int ticket = atomicAdd(&g_count, 1u);
        amLast = (ticket == (unsigned int)gridDim.x - 1u);
    }
    __syncthreads();

    // finishing block computes the loss scalar. NO state mutation here —
    // all resets happen in pack_kernel of the next replay.
    if (amLast && threadIdx.x == 0) {
        double sumsq  = *((volatile double*)&g_sum_sq);
        double sum3   = *((volatile double*)&g_sum_t3);
        double sumlog = 0.0;
        int nlg = S / 256;
        for (int w = 0; w < nlg; w++) sumlog += g_lgpart[w];
        double Sd = (double)S;
        out[0] = (float)(ALPHA * sumsq - Sd * sumlog + sum3 / (Sd * Sd));
    }
}

// ---------------- launch ----------------
extern "C" void kernel_launch(void* const* d_in, const int* in_sizes, int n_in,
                              void* d_out, int out_size) {
    const float* inp = (const float*)d_in[0];
    const float* tgt = (const float*)d_in[1];
    float* out = (float*)d_out;

    long long n = in_sizes[0];
    int S = 1;
    while ((long long)(S + 1) * (S + 1) <= n) S++;   // integer sqrt (S = 4096)
    if (S > MAXS) S = MAXS;

    pack_kernel<<<S / 256, 256>>>(inp, tgt, S);
    main_kernel<<<GRID, 256>>>(inp, tgt, out, S);
}

// round 5
// speedup vs baseline: 1.3768x; 1.0016x over previous
#include <cuda_runtime.h>
#include <math.h>

// LineFinderLoss, S = 4096 (square). Output tuple packed: d_out[0] = loss,
// d_out[1 + i*S + j] = cost[i][j].
//
// cost[i][j] = 0.5*((in[i,0]-tg[j,0])^2 + (in[i,1]-tg[j,1])^2)
// loss = ALPHA*sum((in-tg)^2) - S*sum_n log(in[n,4]) + sum_ij (in[j,3]-tg[i,j])^2 / S^2

#define MAXS    4096
#define ALPHA   0.01
#define RTILE   4        // rows per tile
#define CSLICES 4        // column slices (S / (256 threads * 4 floats))
#define GRID    1184     // 148 SMs * 8 resident blocks

// ---------------- device scratch (no allocations allowed) ----------------
// Shifted packed columns: g_t0s[k] = target[k-1, 0]  (k = 1..S), g_t0s[0] junk.
__device__ float  g_t0s[MAXS + 4];
__device__ float  g_t1s[MAXS + 4];
__device__ float  g_ic3[MAXS + 4];       // input[:,3] (unshifted)
__device__ float  g_a0[MAXS];            // input[:,0]  (row scalars, L1-resident)
__device__ float  g_a1[MAXS];            // input[:,1]
__device__ double g_lgpart[MAXS / 256];  // per-pack-block partial of sum log(in[:,4])
__device__ double g_sum_sq;
__device__ double g_sum_t3;
__device__ unsigned int g_ticket;        // dynamic tile counter
__device__ unsigned int g_count;         // completion counter

// ---------------- kernel 1: reset state + gather columns + partial log-sum --
// Runs strictly before main_kernel on the same stream every replay; all replay
// state resets live here, ordered by the kernel boundary.
__global__ void pack_kernel(const float* __restrict__ inp,
                            const float* __restrict__ tgt, int S) {
    if (blockIdx.x == 0 && threadIdx.x == 0) {
        g_ticket = 0u;
        g_count  = 0u;
        g_sum_sq = 0.0;
        g_sum_t3 = 0.0;
    }
    int r = blockIdx.x * blockDim.x + threadIdx.x;
    float lg = 0.0f;
    if (r < S) {
        size_t base = (size_t)r * S;
        g_t0s[r + 1] = tgt[base + 0];
        g_t1s[r + 1] = tgt[base + 1];
        g_a0[r]      = inp[base + 0];
        g_a1[r]      = inp[base + 1];
        g_ic3[r]     = inp[base + 3];
        lg = logf(inp[base + 4]);
        if (r == 0) { g_t0s[0] = 0.0f; g_t1s[0] = 0.0f; }
    }
    #pragma unroll
    for (int off = 16; off > 0; off >>= 1)
        lg += __shfl_down_sync(0xffffffffu, lg, off);
    __shared__ float ws[8];
    int lane = threadIdx.x & 31, wid = threadIdx.x >> 5;
    if (lane == 0) ws[wid] = lg;
    __syncthreads();
    if (threadIdx.x == 0) {
        float s = 0.0f;
        #pragma unroll
        for (int w = 0; w < 8; w++) s += ws[w];
        g_lgpart[blockIdx.x] = (double)s;
    }
}

// ---------------- kernel 2: persistent, dynamically-balanced stream pass ---
// 1184 resident blocks pop 4-row x 1024-col tiles from a global ticket
// (hard-bounded loop: terminates even on corrupt state). Row scalars a0/a1
// come from small packed arrays (L1 hits), reduction accumulators are split
// by row parity to halve the FMA dependency chain. Cost stores: thread j4
// writes cols [4*j4-1 .. 4*j4+2] as an aligned float4 at (out + row*S + 4*j4)
// since out[0] is the loss scalar; pre-shifted t0s/t1s keep loads aligned.
__global__ __launch_bounds__(256, 8)
void main_kernel(const float* __restrict__ inp,
                 const float* __restrict__ tgt,
                 float* __restrict__ out, int S) {
    const int tid    = threadIdx.x;
    const int lastj4 = (S >> 2) - 1;
    const int ntiles = CSLICES * (S / RTILE);

    __shared__ unsigned int sh_t;
    float acc_sq0 = 0.0f, acc_sq1 = 0.0f;
    float acc_t30 = 0.0f, acc_t31 = 0.0f;

    for (int safety = 0; safety < ntiles + 2; safety++) {
        if (tid == 0) sh_t = atomicAdd(&g_ticket, 1u);
        __syncthreads();
        const unsigned int t = sh_t;
        __syncthreads();
        if (t >= (unsigned int)ntiles) break;

        const int cs   = (int)(t & (CSLICES - 1));
        const int row0 = (int)(t >> 2) * RTILE;
        const int j4   = cs * 256 + tid;
        const bool isFirst = (j4 == 0);
        const bool isLast  = (j4 == lastj4);

        // column-resident data (L1/L2 hits), reused across RTILE rows
        const float4 t0s = ((const float4*)g_t0s)[j4];  // t0[4j-1..4j+2]
        const float4 t1s = ((const float4*)g_t1s)[j4];
        const float4 c3  = ((const float4*)g_ic3)[j4];  // in[4j..4j+3, 3]

        #pragma unroll
        for (int r = 0; r < RTILE; r++) {
            const int row = row0 + r;
            const size_t base = (size_t)row * S;
            const float4 in = __ldcs((const float4*)(inp + base) + j4);
            const float4 tg = __ldcs((const float4*)(tgt + base) + j4);
            const float a0 = g_a0[row];   // broadcast, L1-resident
            const float a1 = g_a1[row];

            float* accq = (r & 1) ? &acc_sq1 : &acc_sq0;
            float* acct = (r & 1) ? &acc_t31 : &acc_t30;
            float d, e;
            d = in.x - tg.x; *accq = fmaf(d, d, *accq);
            e = c3.x - tg.x; *acct = fmaf(e, e, *acct);
            d = in.y - tg.y; *accq = fmaf(d, d, *accq);
            e = c3.y - tg.y; *acct = fmaf(e, e, *acct);
            d = in.z - tg.z; *accq = fmaf(d, d, *accq);
            e = c3.z - tg.z; *acct = fmaf(e, e, *acct);
            d = in.w - tg.w; *accq = fmaf(d, d, *accq);
            e = c3.w - tg.w; *acct = fmaf(e, e, *acct);

            float4 cv;
            float u, v;
            u = a0 - t0s.x; v = a1 - t1s.x; cv.x = 0.5f * fmaf(u, u, v * v);
            u = a0 - t0s.y; v = a1 - t1s.y; cv.y = 0.5f * fmaf(u, u, v * v);
            u = a0 - t0s.z; v = a1 - t1s.z; cv.z = 0.5f * fmaf(u, u, v * v);
            u = a0 - t0s.w; v = a1 - t1s.w; cv.w = 0.5f * fmaf(u, u, v * v);

            if (!isFirst) {
                // out + base + 4*j4 == cost + base + (4*j4 - 1), 16B aligned
                __stcs((float4*)(out + base) + j4, cv);
            } else {
                float* crow = out + 1 + base;   // cost row start (cols 0..2)
                crow[0] = cv.y; crow[1] = cv.z; crow[2] = cv.w;
            }
            if (isLast) {
                u = a0 - g_t0s[S]; v = a1 - g_t1s[S];
                out[1 + base + (size_t)(S - 1)] = 0.5f * fmaf(u, u, v * v);
            }
        }
    }

    float acc_sq = acc_sq0 + acc_sq1;
    float acc_t3 = acc_t30 + acc_t31;

    // block reduce (after all tiles)
    #pragma unroll
    for (int off = 16; off > 0; off >>= 1) {
        acc_sq += __shfl_down_sync(0xffffffffu, acc_sq, off);
        acc_t3 += __shfl_down_sync(0xffffffffu, acc_t3, off);
    }
    __shared__ float s_sq[8], s_t3[8];
    int lane = threadIdx.x & 31, wid = threadIdx.x >> 5;
    if (lane == 0) { s_sq[wid] = acc_sq; s_t3[wid] = acc_t3; }
    __syncthreads();

    __shared__ bool amLast;
    if (threadIdx.x == 0) {
        float r1 = 0.0f, r2 = 0.0f;
        #pragma unroll
        for (int w = 0; w < 8; w++) { r1 += s_sq[w]; r2 += s_t3[w]; }
        atomicAdd(&g_sum_sq, (double)r1);
        atomicAdd(&g_sum_t3, (double)r2);
        __threadfence();
        unsigned int ticket = atomicAdd(&g_count, 1u);
        amLast = (ticket == (unsigned int)gridDim.x - 1u);
    }
    __syncthreads();

    // finishing block computes the loss scalar. NO state mutation here —
    // all resets happen in pack_kernel of the next replay.
    if (amLast && threadIdx.x == 0) {
        double sumsq  = *((volatile double*)&g_sum_sq);
        double sum3   = *((volatile double*)&g_sum_t3);
        double sumlog = 0.0;
        int nlg = S / 256;
        for (int w = 0; w < nlg; w++) sumlog += g_lgpart[w];
        double Sd = (double)S;
        out[0] = (float)(ALPHA * sumsq - Sd * sumlog + sum3 / (Sd * Sd));
    }
}

// ---------------- launch ----------------
extern "C" void kernel_launch(void* const* d_in, const int* in_sizes, int n_in,
                              void* d_out, int out_size) {
    const float* inp = (const float*)d_in[0];
    const float* tgt = (const float*)d_in[1];
    float* out = (float*)d_out;

    long long n = in_sizes[0];
    int S = 1;
    while ((long long)(S + 1) * (S + 1) <= n) S++;   // integer sqrt (S = 4096)
    if (S > MAXS) S = MAXS;

    pack_kernel<<<S / 256, 256>>>(inp, tgt, S);
    main_kernel<<<GRID, 256>>>(inp, tgt, out, S);
}